// round 8
// baseline (speedup 1.0000x reference)
#include <cuda_runtime.h>
#include <cuda_bf16.h>

// Problem constants (fixed by the reference setup)
#define MAXN 50000
#define MAXE 800000
#define FEAT 128
#define NHEAD 4
#define CDIM 32
#define NGRAPH 64
#define NEG_SLOPE 0.2f
#define SCAN_BS 256

// ---------------- device scratch (no allocations allowed) ----------------
__device__ __align__(256) float g_xp[MAXN * FEAT];        // projected features [N,128]
__device__ __align__(256) float g_asrc[MAXN * NHEAD];     // per-node src logits [N,4]
__device__ __align__(256) float g_adst[MAXN * NHEAD];     // per-node dst logits [N,4]
__device__ __align__(256) int   g_deg[MAXN];              // in-degree histogram
__device__ __align__(256) int   g_off[MAXN + 1];          // CSR offsets
__device__ __align__(256) int   g_cursor[MAXN];           // CSR fill cursors
__device__ __align__(256) int   g_esrc[MAXE];             // CSR: src node per edge slot
__device__ __align__(256) float g_pooled[NGRAPH * FEAT];  // per-graph feature sums
__device__ __align__(256) int   g_bsum[(MAXN + SCAN_BS - 1) / SCAN_BS];  // block sums
__device__ __align__(256) int   g_bpre[(MAXN + SCAN_BS - 1) / SCAN_BS];  // block prefixes

// ---------------- K0: zero scratch that must start at 0 ----------------
__global__ void zero_kernel(int Nn) {
    int idx = blockIdx.x * blockDim.x + threadIdx.x;
    if (idx < Nn) g_deg[idx] = 0;
    if (idx < NGRAPH * FEAT) g_pooled[idx] = 0.f;
}

// ---------------- K1: xp = x @ W, fused att_src/att_dst dots ----------------
__global__ __launch_bounds__(256) void gemm_att_kernel(
    const float* __restrict__ x, const float* __restrict__ W,
    const float* __restrict__ att_s, const float* __restrict__ att_d, int Nn)
{
    __shared__ float sW[32 * FEAT];     // 16KB: one K-chunk of W (rows k..k+31)
    __shared__ float sx[32 * 129];      // 16.5KB padded x tile
    int tid = threadIdx.x;
    int row0 = blockIdx.x * 32;

    for (int idx = tid; idx < 32 * 32; idx += 256) {
        int r = idx >> 5, c4 = idx & 31;
        float4 v = make_float4(0.f, 0.f, 0.f, 0.f);
        if (row0 + r < Nn) v = ((const float4*)(x + (size_t)(row0 + r) * FEAT))[c4];
        float* p = &sx[r * 129 + c4 * 4];
        p[0] = v.x; p[1] = v.y; p[2] = v.z; p[3] = v.w;
    }

    int cg = tid & 31;            // column group: output cols cg*4 .. cg*4+3
    int rb = (tid >> 5) * 4;      // rows rb .. rb+3
    float a00=0,a01=0,a02=0,a03=0, a10=0,a11=0,a12=0,a13=0;
    float a20=0,a21=0,a22=0,a23=0, a30=0,a31=0,a32=0,a33=0;

    const float4* W4 = (const float4*)W;

    for (int kc = 0; kc < 4; kc++) {
        __syncthreads();
        for (int idx = tid; idx < 32 * 32; idx += 256) {
            float4 wv = W4[kc * (32 * 32) + idx];
            float* p = &sW[idx * 4];
            p[0] = wv.x; p[1] = wv.y; p[2] = wv.z; p[3] = wv.w;
        }
        __syncthreads();

#pragma unroll 8
        for (int kk = 0; kk < 32; kk++) {
            int k = kc * 32 + kk;
            const float* wp = &sW[kk * FEAT + cg * 4];
            float w0 = wp[0], w1 = wp[1], w2 = wp[2], w3 = wp[3];
            float xa = sx[(rb + 0) * 129 + k];
            float xb = sx[(rb + 1) * 129 + k];
            float xc = sx[(rb + 2) * 129 + k];
            float xd = sx[(rb + 3) * 129 + k];
            a00 += xa * w0; a01 += xa * w1; a02 += xa * w2; a03 += xa * w3;
            a10 += xb * w0; a11 += xb * w1; a12 += xb * w2; a13 += xb * w3;
            a20 += xc * w0; a21 += xc * w1; a22 += xc * w2; a23 += xc * w3;
            a30 += xd * w0; a31 += xd * w1; a32 += xd * w2; a33 += xd * w3;
        }
    }

    if (row0 + rb + 0 < Nn) ((float4*)(g_xp + (size_t)(row0+rb+0)*FEAT))[cg] = make_float4(a00,a01,a02,a03);
    if (row0 + rb + 1 < Nn) ((float4*)(g_xp + (size_t)(row0+rb+1)*FEAT))[cg] = make_float4(a10,a11,a12,a13);
    if (row0 + rb + 2 < Nn) ((float4*)(g_xp + (size_t)(row0+rb+2)*FEAT))[cg] = make_float4(a20,a21,a22,a23);
    if (row0 + rb + 3 < Nn) ((float4*)(g_xp + (size_t)(row0+rb+3)*FEAT))[cg] = make_float4(a30,a31,a32,a33);

    __syncthreads();
    {
        float* p0 = &sx[(rb + 0) * 129 + cg * 4];
        p0[0]=a00; p0[1]=a01; p0[2]=a02; p0[3]=a03;
        float* p1 = &sx[(rb + 1) * 129 + cg * 4];
        p1[0]=a10; p1[1]=a11; p1[2]=a12; p1[3]=a13;
        float* p2 = &sx[(rb + 2) * 129 + cg * 4];
        p2[0]=a20; p2[1]=a21; p2[2]=a22; p2[3]=a23;
        float* p3 = &sx[(rb + 3) * 129 + cg * 4];
        p3[0]=a30; p3[1]=a31; p3[2]=a32; p3[3]=a33;
    }
    __syncthreads();

    if (tid < 128) {
        int h = tid >> 5, rr = tid & 31;
        if (row0 + rr < Nn) {
            float ds = 0.f, dd = 0.f;
#pragma unroll
            for (int c = 0; c < CDIM; c++) {
                float v = sx[rr * 129 + h * CDIM + c];
                ds += v * att_s[h * CDIM + c];
                dd += v * att_d[h * CDIM + c];
            }
            g_asrc[(row0 + rr) * NHEAD + h] = ds;
            g_adst[(row0 + rr) * NHEAD + h] = dd;
        }
    }
}

// ---------------- K2: in-degree histogram (edge_index is int32) ----------------
__global__ void hist_kernel(const int* __restrict__ ei, int E) {
    int idx = blockIdx.x * blockDim.x + threadIdx.x;
    if (idx < E) atomicAdd(&g_deg[ei[E + idx]], 1);
}

// ---------------- K3a: per-block degree sums ----------------
__global__ __launch_bounds__(SCAN_BS) void scan_pass1(int Nn) {
    __shared__ int sh[SCAN_BS];
    int i = blockIdx.x * SCAN_BS + threadIdx.x;
    int v = (i < Nn) ? g_deg[i] : 0;
    sh[threadIdx.x] = v;
    __syncthreads();
    for (int d = SCAN_BS / 2; d > 0; d >>= 1) {
        if (threadIdx.x < d) sh[threadIdx.x] += sh[threadIdx.x + d];
        __syncthreads();
    }
    if (threadIdx.x == 0) g_bsum[blockIdx.x] = sh[0];
}

// ---------------- K3b: scan of block sums (nb <= 256) ----------------
__global__ __launch_bounds__(SCAN_BS) void scan_pass2(int nb) {
    __shared__ int sh[SCAN_BS];
    int t = threadIdx.x;
    sh[t] = (t < nb) ? g_bsum[t] : 0;
    __syncthreads();
    for (int d = 1; d < SCAN_BS; d <<= 1) {
        int v = (t >= d) ? sh[t - d] : 0;
        __syncthreads();
        sh[t] += v;
        __syncthreads();
    }
    if (t < nb) g_bpre[t] = (t > 0) ? sh[t - 1] : 0;   // exclusive
}

// ---------------- K3c: per-block exclusive scan + offsets + cursors ----------------
__global__ __launch_bounds__(SCAN_BS) void scan_pass3(int Nn) {
    __shared__ int sh[SCAN_BS];
    int t = threadIdx.x;
    int i = blockIdx.x * SCAN_BS + t;
    int v = (i < Nn) ? g_deg[i] : 0;
    sh[t] = v;
    __syncthreads();
    for (int d = 1; d < SCAN_BS; d <<= 1) {
        int u = (t >= d) ? sh[t - d] : 0;
        __syncthreads();
        sh[t] += u;
        __syncthreads();
    }
    int incl = sh[t];
    int base = g_bpre[blockIdx.x];
    int pre = base + incl - v;          // exclusive prefix
    if (i < Nn) {
        g_off[i] = pre;
        g_cursor[i] = pre;
        if (i == Nn - 1) g_off[Nn] = pre + v;
    }
}

// ---------------- K5: CSR fill (src per slot) ----------------
__global__ void csr_kernel(const int* __restrict__ ei, int E) {
    int idx = blockIdx.x * blockDim.x + threadIdx.x;
    if (idx < E) {
        int d = ei[E + idx];
        int s = ei[idx];
        int pos = atomicAdd(&g_cursor[d], 1);
        g_esrc[pos] = s;
    }
}

// ---------------- K6: fused softmax + aggregate + relu + pool ----------------
// One warp per dst node. Lane owns cols [4*lane,4*lane+4) (head lane>>3).
// 4-edge batches: all index loads issued first, then all gathers, to raise MLP.
__global__ __launch_bounds__(256) void agg_kernel(
    const int* __restrict__ batch, const float* __restrict__ bias, int Nn)
{
    int warp = (blockIdx.x * blockDim.x + threadIdx.x) >> 5;
    int lane = threadIdx.x & 31;
    if (warp >= Nn) return;
    int i = warp;
    int h = lane >> 3;           // head of my 4 columns

    float adh = g_adst[i * 4 + h];
    float ash = g_asrc[i * 4 + h];

    // self-loop weight for my head (softmax shift cancels exactly)
    float es = ash + adh;
    float wsh = __expf(fmaxf(es, NEG_SLOPE * es));

    float4 xi4 = *(const float4*)(g_xp + (size_t)i * FEAT + lane * 4);
    float4 acc;
    acc.x = wsh * xi4.x; acc.y = wsh * xi4.y; acc.z = wsh * xi4.z; acc.w = wsh * xi4.w;
    float s = wsh;               // every lane of head h accumulates the full head sum

    int beg = g_off[i], end = g_off[i + 1];
    int j = beg;

    // ---- 4-edge batches: maximize loads in flight ----
    for (; j + 4 <= end; j += 4) {
        // 4 independent index loads (uniform across warp)
        int sj0 = g_esrc[j + 0];
        int sj1 = g_esrc[j + 1];
        int sj2 = g_esrc[j + 2];
        int sj3 = g_esrc[j + 3];
        // 4 independent logit loads + 4 independent row gathers, all issued
        // before any consumer math
        float f0 = g_asrc[sj0 * 4 + h];
        float f1 = g_asrc[sj1 * 4 + h];
        float f2 = g_asrc[sj2 * 4 + h];
        float f3 = g_asrc[sj3 * 4 + h];
        float4 x0 = *(const float4*)(g_xp + (size_t)sj0 * FEAT + lane * 4);
        float4 x1 = *(const float4*)(g_xp + (size_t)sj1 * FEAT + lane * 4);
        float4 x2 = *(const float4*)(g_xp + (size_t)sj2 * FEAT + lane * 4);
        float4 x3 = *(const float4*)(g_xp + (size_t)sj3 * FEAT + lane * 4);

        f0 += adh; f1 += adh; f2 += adh; f3 += adh;
        float w0 = __expf(fmaxf(f0, NEG_SLOPE * f0));
        float w1 = __expf(fmaxf(f1, NEG_SLOPE * f1));
        float w2 = __expf(fmaxf(f2, NEG_SLOPE * f2));
        float w3 = __expf(fmaxf(f3, NEG_SLOPE * f3));
        s += w0; s += w1; s += w2; s += w3;

        acc.x += w0 * x0.x; acc.y += w0 * x0.y; acc.z += w0 * x0.z; acc.w += w0 * x0.w;
        acc.x += w1 * x1.x; acc.y += w1 * x1.y; acc.z += w1 * x1.z; acc.w += w1 * x1.w;
        acc.x += w2 * x2.x; acc.y += w2 * x2.y; acc.z += w2 * x2.z; acc.w += w2 * x2.w;
        acc.x += w3 * x3.x; acc.y += w3 * x3.y; acc.z += w3 * x3.z; acc.w += w3 * x3.w;
    }
    // ---- remainder ----
    for (; j < end; j++) {
        int sj = g_esrc[j];
        float f = g_asrc[sj * 4 + h] + adh;
        float w = __expf(fmaxf(f, NEG_SLOPE * f));
        s += w;
        float4 xr = *(const float4*)(g_xp + (size_t)sj * FEAT + lane * 4);
        acc.x += w * xr.x; acc.y += w * xr.y; acc.z += w * xr.z; acc.w += w * xr.w;
    }

    float inv = 1.0f / s;
    float4 b4 = ((const float4*)bias)[lane];
    float o0 = fmaxf(acc.x * inv + b4.x, 0.f);
    float o1 = fmaxf(acc.y * inv + b4.y, 0.f);
    float o2 = fmaxf(acc.z * inv + b4.z, 0.f);
    float o3 = fmaxf(acc.w * inv + b4.w, 0.f);

    int g = batch[i];
    float* pg = g_pooled + g * FEAT + lane * 4;
    atomicAdd(pg + 0, o0);
    atomicAdd(pg + 1, o1);
    atomicAdd(pg + 2, o2);
    atomicAdd(pg + 3, o3);
}

// ---------------- K7: mean + final linear ----------------
__global__ void final_kernel(const int* __restrict__ batch, int Nn,
                             const float* __restrict__ Wl, const float* __restrict__ bl,
                             float* __restrict__ out)
{
    int t = threadIdx.x;
    if (t >= NGRAPH * 2) return;
    int g = t >> 1, o = t & 1;
    int lo = 0, hi = Nn;
    while (lo < hi) { int m = (lo + hi) >> 1; if (batch[m] < g) lo = m + 1; else hi = m; }
    int c0 = lo;
    lo = 0; hi = Nn;
    while (lo < hi) { int m = (lo + hi) >> 1; if (batch[m] < g + 1) lo = m + 1; else hi = m; }
    int cnt = lo - c0;
    float fc = (float)max(cnt, 1);
    float sum = 0.f;
#pragma unroll 4
    for (int k = 0; k < FEAT; k++) sum += g_pooled[g * FEAT + k] * Wl[k * 2 + o];
    out[g * 2 + o] = sum / fc + bl[o];
}

// ---------------- launch ----------------
extern "C" void kernel_launch(void* const* d_in, const int* in_sizes, int n_in,
                              void* d_out, int out_size)
{
    const float* x     = (const float*)d_in[0];
    const int*   ei    = (const int*)d_in[1];     // int32 on the wire
    const int*   batch = (const int*)d_in[2];     // int32 on the wire
    const float* W     = (const float*)d_in[3];
    const float* att_s = (const float*)d_in[4];
    const float* att_d = (const float*)d_in[5];
    const float* bias  = (const float*)d_in[6];
    const float* Wl    = (const float*)d_in[7];
    const float* bl    = (const float*)d_in[8];
    float* out = (float*)d_out;

    int N = in_sizes[0] / FEAT;
    int E = in_sizes[1] / 2;
    int nb = (N + SCAN_BS - 1) / SCAN_BS;

    zero_kernel<<<(N + 255) / 256, 256>>>(N);
    gemm_att_kernel<<<(N + 31) / 32, 256>>>(x, W, att_s, att_d, N);
    hist_kernel<<<(E + 255) / 256, 256>>>(ei, E);
    scan_pass1<<<nb, SCAN_BS>>>(N);
    scan_pass2<<<1, SCAN_BS>>>(nb);
    scan_pass3<<<nb, SCAN_BS>>>(N);
    csr_kernel<<<(E + 255) / 256, 256>>>(ei, E);
    {
        long long threads = (long long)N * 32;
        int blocks = (int)((threads + 255) / 256);
        agg_kernel<<<blocks, 256>>>(batch, bias, N);
    }
    final_kernel<<<1, 128>>>(batch, N, Wl, bl, out);
}

// round 9
// speedup vs baseline: 1.2032x; 1.2032x over previous
#include <cuda_runtime.h>
#include <cuda_bf16.h>

// Problem constants (fixed by the reference setup)
#define MAXN 50000
#define MAXE 800000
#define FEAT 128
#define NHEAD 4
#define CDIM 32
#define NGRAPH 64
#define NEG_SLOPE 0.2f
#define SCAN_BS 256

// ---------------- device scratch (no allocations allowed) ----------------
__device__ __align__(256) float g_xp[MAXN * FEAT];        // projected features [N,128]
__device__ __align__(256) float g_asrc[MAXN * NHEAD];     // per-node src logits [N,4]
__device__ __align__(256) float g_adst[MAXN * NHEAD];     // per-node dst logits [N,4]
__device__ __align__(256) int   g_deg[MAXN];              // in-degree histogram
__device__ __align__(256) int   g_off[MAXN + 1];          // CSR offsets
__device__ __align__(256) int   g_cursor[MAXN];           // CSR fill cursors
__device__ __align__(256) int   g_esrc[MAXE];             // CSR: src node per edge slot
__device__ __align__(256) float g_pooled[NGRAPH * FEAT];  // per-graph feature sums
__device__ __align__(256) int   g_bsum[(MAXN + SCAN_BS - 1) / SCAN_BS];  // block sums
__device__ __align__(256) int   g_bpre[(MAXN + SCAN_BS - 1) / SCAN_BS];  // block prefixes

// ---------------- K0: zero scratch that must start at 0 ----------------
__global__ void zero_kernel(int Nn) {
    int idx = blockIdx.x * blockDim.x + threadIdx.x;
    if (idx < Nn) g_deg[idx] = 0;
    if (idx < NGRAPH * FEAT) g_pooled[idx] = 0.f;
}

// ---------------- K1: xp = x @ W, fused att_src/att_dst dots ----------------
__global__ __launch_bounds__(256) void gemm_att_kernel(
    const float* __restrict__ x, const float* __restrict__ W,
    const float* __restrict__ att_s, const float* __restrict__ att_d, int Nn)
{
    __shared__ float sW[32 * FEAT];     // 16KB: one K-chunk of W (rows k..k+31)
    __shared__ float sx[32 * 129];      // 16.5KB padded x tile
    int tid = threadIdx.x;
    int row0 = blockIdx.x * 32;

    for (int idx = tid; idx < 32 * 32; idx += 256) {
        int r = idx >> 5, c4 = idx & 31;
        float4 v = make_float4(0.f, 0.f, 0.f, 0.f);
        if (row0 + r < Nn) v = ((const float4*)(x + (size_t)(row0 + r) * FEAT))[c4];
        float* p = &sx[r * 129 + c4 * 4];
        p[0] = v.x; p[1] = v.y; p[2] = v.z; p[3] = v.w;
    }

    int cg = tid & 31;            // column group: output cols cg*4 .. cg*4+3
    int rb = (tid >> 5) * 4;      // rows rb .. rb+3
    float a00=0,a01=0,a02=0,a03=0, a10=0,a11=0,a12=0,a13=0;
    float a20=0,a21=0,a22=0,a23=0, a30=0,a31=0,a32=0,a33=0;

    const float4* W4 = (const float4*)W;

    for (int kc = 0; kc < 4; kc++) {
        __syncthreads();
        for (int idx = tid; idx < 32 * 32; idx += 256) {
            float4 wv = W4[kc * (32 * 32) + idx];
            float* p = &sW[idx * 4];
            p[0] = wv.x; p[1] = wv.y; p[2] = wv.z; p[3] = wv.w;
        }
        __syncthreads();

#pragma unroll 8
        for (int kk = 0; kk < 32; kk++) {
            int k = kc * 32 + kk;
            const float* wp = &sW[kk * FEAT + cg * 4];
            float w0 = wp[0], w1 = wp[1], w2 = wp[2], w3 = wp[3];
            float xa = sx[(rb + 0) * 129 + k];
            float xb = sx[(rb + 1) * 129 + k];
            float xc = sx[(rb + 2) * 129 + k];
            float xd = sx[(rb + 3) * 129 + k];
            a00 += xa * w0; a01 += xa * w1; a02 += xa * w2; a03 += xa * w3;
            a10 += xb * w0; a11 += xb * w1; a12 += xb * w2; a13 += xb * w3;
            a20 += xc * w0; a21 += xc * w1; a22 += xc * w2; a23 += xc * w3;
            a30 += xd * w0; a31 += xd * w1; a32 += xd * w2; a33 += xd * w3;
        }
    }

    if (row0 + rb + 0 < Nn) ((float4*)(g_xp + (size_t)(row0+rb+0)*FEAT))[cg] = make_float4(a00,a01,a02,a03);
    if (row0 + rb + 1 < Nn) ((float4*)(g_xp + (size_t)(row0+rb+1)*FEAT))[cg] = make_float4(a10,a11,a12,a13);
    if (row0 + rb + 2 < Nn) ((float4*)(g_xp + (size_t)(row0+rb+2)*FEAT))[cg] = make_float4(a20,a21,a22,a23);
    if (row0 + rb + 3 < Nn) ((float4*)(g_xp + (size_t)(row0+rb+3)*FEAT))[cg] = make_float4(a30,a31,a32,a33);

    __syncthreads();
    {
        float* p0 = &sx[(rb + 0) * 129 + cg * 4];
        p0[0]=a00; p0[1]=a01; p0[2]=a02; p0[3]=a03;
        float* p1 = &sx[(rb + 1) * 129 + cg * 4];
        p1[0]=a10; p1[1]=a11; p1[2]=a12; p1[3]=a13;
        float* p2 = &sx[(rb + 2) * 129 + cg * 4];
        p2[0]=a20; p2[1]=a21; p2[2]=a22; p2[3]=a23;
        float* p3 = &sx[(rb + 3) * 129 + cg * 4];
        p3[0]=a30; p3[1]=a31; p3[2]=a32; p3[3]=a33;
    }
    __syncthreads();

    if (tid < 128) {
        int h = tid >> 5, rr = tid & 31;
        if (row0 + rr < Nn) {
            float ds = 0.f, dd = 0.f;
#pragma unroll
            for (int c = 0; c < CDIM; c++) {
                float v = sx[rr * 129 + h * CDIM + c];
                ds += v * att_s[h * CDIM + c];
                dd += v * att_d[h * CDIM + c];
            }
            g_asrc[(row0 + rr) * NHEAD + h] = ds;
            g_adst[(row0 + rr) * NHEAD + h] = dd;
        }
    }
}

// ---------------- K2: in-degree histogram (edge_index is int32) ----------------
__global__ void hist_kernel(const int* __restrict__ ei, int E) {
    int idx = blockIdx.x * blockDim.x + threadIdx.x;
    if (idx < E) atomicAdd(&g_deg[ei[E + idx]], 1);
}

// ---------------- K3a: per-block degree sums ----------------
__global__ __launch_bounds__(SCAN_BS) void scan_pass1(int Nn) {
    __shared__ int sh[SCAN_BS];
    int i = blockIdx.x * SCAN_BS + threadIdx.x;
    int v = (i < Nn) ? g_deg[i] : 0;
    sh[threadIdx.x] = v;
    __syncthreads();
    for (int d = SCAN_BS / 2; d > 0; d >>= 1) {
        if (threadIdx.x < d) sh[threadIdx.x] += sh[threadIdx.x + d];
        __syncthreads();
    }
    if (threadIdx.x == 0) g_bsum[blockIdx.x] = sh[0];
}

// ---------------- K3b: scan of block sums (nb <= 256) ----------------
__global__ __launch_bounds__(SCAN_BS) void scan_pass2(int nb) {
    __shared__ int sh[SCAN_BS];
    int t = threadIdx.x;
    sh[t] = (t < nb) ? g_bsum[t] : 0;
    __syncthreads();
    for (int d = 1; d < SCAN_BS; d <<= 1) {
        int v = (t >= d) ? sh[t - d] : 0;
        __syncthreads();
        sh[t] += v;
        __syncthreads();
    }
    if (t < nb) g_bpre[t] = (t > 0) ? sh[t - 1] : 0;   // exclusive
}

// ---------------- K3c: per-block exclusive scan + offsets + cursors ----------------
__global__ __launch_bounds__(SCAN_BS) void scan_pass3(int Nn) {
    __shared__ int sh[SCAN_BS];
    int t = threadIdx.x;
    int i = blockIdx.x * SCAN_BS + t;
    int v = (i < Nn) ? g_deg[i] : 0;
    sh[t] = v;
    __syncthreads();
    for (int d = 1; d < SCAN_BS; d <<= 1) {
        int u = (t >= d) ? sh[t - d] : 0;
        __syncthreads();
        sh[t] += u;
        __syncthreads();
    }
    int incl = sh[t];
    int base = g_bpre[blockIdx.x];
    int pre = base + incl - v;          // exclusive prefix
    if (i < Nn) {
        g_off[i] = pre;
        g_cursor[i] = pre;
        if (i == Nn - 1) g_off[Nn] = pre + v;
    }
}

// ---------------- K5: CSR fill (src per slot) ----------------
__global__ void csr_kernel(const int* __restrict__ ei, int E) {
    int idx = blockIdx.x * blockDim.x + threadIdx.x;
    if (idx < E) {
        int d = ei[E + idx];
        int s = ei[idx];
        int pos = atomicAdd(&g_cursor[d], 1);
        g_esrc[pos] = s;
    }
}

// ---------------- K6: fused softmax + aggregate + relu + pool ----------------
// TWO dst nodes per warp: two independent load chains in flight doubles MLP
// without fighting ptxas's pipeliner (R6 loop body kept verbatim per node).
__global__ __launch_bounds__(256) void agg_kernel(
    const int* __restrict__ batch, const float* __restrict__ bias, int Nn)
{
    int warp = (blockIdx.x * blockDim.x + threadIdx.x) >> 5;
    int lane = threadIdx.x & 31;
    int i0 = warp * 2;
    if (i0 >= Nn) return;
    int i1 = i0 + 1;
    bool has1 = (i1 < Nn);
    int h = lane >> 3;           // head of my 4 columns

    // ---- node 0 setup ----
    float adh0 = g_adst[i0 * 4 + h];
    float es0 = g_asrc[i0 * 4 + h] + adh0;
    float wsh0 = __expf(fmaxf(es0, NEG_SLOPE * es0));
    float4 xi0 = *(const float4*)(g_xp + (size_t)i0 * FEAT + lane * 4);
    float4 acc0 = make_float4(wsh0 * xi0.x, wsh0 * xi0.y, wsh0 * xi0.z, wsh0 * xi0.w);
    float s0 = wsh0;

    // ---- node 1 setup (predicated) ----
    float adh1 = 0.f, wsh1 = 0.f;
    float4 acc1 = make_float4(0.f, 0.f, 0.f, 0.f);
    float s1 = 0.f;
    if (has1) {
        adh1 = g_adst[i1 * 4 + h];
        float es1 = g_asrc[i1 * 4 + h] + adh1;
        wsh1 = __expf(fmaxf(es1, NEG_SLOPE * es1));
        float4 xi1 = *(const float4*)(g_xp + (size_t)i1 * FEAT + lane * 4);
        acc1.x = wsh1 * xi1.x; acc1.y = wsh1 * xi1.y;
        acc1.z = wsh1 * xi1.z; acc1.w = wsh1 * xi1.w;
        s1 = wsh1;
    }

    int beg0 = g_off[i0], end0 = g_off[i0 + 1];
    int beg1 = has1 ? g_off[i1] : 0, end1 = has1 ? g_off[i1 + 1] : 0;
    int len0 = end0 - beg0, len1 = end1 - beg1;
    int L = max(len0, len1);

#pragma unroll 2
    for (int t = 0; t < L; t++) {
        // issue both index loads first (independent chains)
        int sj0 = (t < len0) ? g_esrc[beg0 + t] : 0;
        int sj1 = (t < len1) ? g_esrc[beg1 + t] : 0;
        // chain 0
        if (t < len0) {
            float f = g_asrc[sj0 * 4 + h] + adh0;
            float w = __expf(fmaxf(f, NEG_SLOPE * f));
            s0 += w;
            float4 xr = *(const float4*)(g_xp + (size_t)sj0 * FEAT + lane * 4);
            acc0.x += w * xr.x; acc0.y += w * xr.y; acc0.z += w * xr.z; acc0.w += w * xr.w;
        }
        // chain 1
        if (t < len1) {
            float f = g_asrc[sj1 * 4 + h] + adh1;
            float w = __expf(fmaxf(f, NEG_SLOPE * f));
            s1 += w;
            float4 xr = *(const float4*)(g_xp + (size_t)sj1 * FEAT + lane * 4);
            acc1.x += w * xr.x; acc1.y += w * xr.y; acc1.z += w * xr.z; acc1.w += w * xr.w;
        }
    }

    float4 b4 = ((const float4*)bias)[lane];

    {
        float inv = 1.0f / s0;
        float o0 = fmaxf(acc0.x * inv + b4.x, 0.f);
        float o1 = fmaxf(acc0.y * inv + b4.y, 0.f);
        float o2 = fmaxf(acc0.z * inv + b4.z, 0.f);
        float o3 = fmaxf(acc0.w * inv + b4.w, 0.f);
        int g = batch[i0];
        float* pg = g_pooled + g * FEAT + lane * 4;
        atomicAdd(pg + 0, o0);
        atomicAdd(pg + 1, o1);
        atomicAdd(pg + 2, o2);
        atomicAdd(pg + 3, o3);
    }
    if (has1) {
        float inv = 1.0f / s1;
        float o0 = fmaxf(acc1.x * inv + b4.x, 0.f);
        float o1 = fmaxf(acc1.y * inv + b4.y, 0.f);
        float o2 = fmaxf(acc1.z * inv + b4.z, 0.f);
        float o3 = fmaxf(acc1.w * inv + b4.w, 0.f);
        int g = batch[i1];
        float* pg = g_pooled + g * FEAT + lane * 4;
        atomicAdd(pg + 0, o0);
        atomicAdd(pg + 1, o1);
        atomicAdd(pg + 2, o2);
        atomicAdd(pg + 3, o3);
    }
}

// ---------------- K7: mean + final linear ----------------
__global__ void final_kernel(const int* __restrict__ batch, int Nn,
                             const float* __restrict__ Wl, const float* __restrict__ bl,
                             float* __restrict__ out)
{
    int t = threadIdx.x;
    if (t >= NGRAPH * 2) return;
    int g = t >> 1, o = t & 1;
    int lo = 0, hi = Nn;
    while (lo < hi) { int m = (lo + hi) >> 1; if (batch[m] < g) lo = m + 1; else hi = m; }
    int c0 = lo;
    lo = 0; hi = Nn;
    while (lo < hi) { int m = (lo + hi) >> 1; if (batch[m] < g + 1) lo = m + 1; else hi = m; }
    int cnt = lo - c0;
    float fc = (float)max(cnt, 1);
    float sum = 0.f;
#pragma unroll 4
    for (int k = 0; k < FEAT; k++) sum += g_pooled[g * FEAT + k] * Wl[k * 2 + o];
    out[g * 2 + o] = sum / fc + bl[o];
}

// ---------------- launch ----------------
extern "C" void kernel_launch(void* const* d_in, const int* in_sizes, int n_in,
                              void* d_out, int out_size)
{
    const float* x     = (const float*)d_in[0];
    const int*   ei    = (const int*)d_in[1];     // int32 on the wire
    const int*   batch = (const int*)d_in[2];     // int32 on the wire
    const float* W     = (const float*)d_in[3];
    const float* att_s = (const float*)d_in[4];
    const float* att_d = (const float*)d_in[5];
    const float* bias  = (const float*)d_in[6];
    const float* Wl    = (const float*)d_in[7];
    const float* bl    = (const float*)d_in[8];
    float* out = (float*)d_out;

    int N = in_sizes[0] / FEAT;
    int E = in_sizes[1] / 2;
    int nb = (N + SCAN_BS - 1) / SCAN_BS;

    zero_kernel<<<(N + 255) / 256, 256>>>(N);
    gemm_att_kernel<<<(N + 31) / 32, 256>>>(x, W, att_s, att_d, N);
    hist_kernel<<<(E + 255) / 256, 256>>>(ei, E);
    scan_pass1<<<nb, SCAN_BS>>>(N);
    scan_pass2<<<1, SCAN_BS>>>(nb);
    scan_pass3<<<nb, SCAN_BS>>>(N);
    csr_kernel<<<(E + 255) / 256, 256>>>(ei, E);
    {
        int nwarps = (N + 1) / 2;
        long long threads = (long long)nwarps * 32;
        int blocks = (int)((threads + 255) / 256);
        agg_kernel<<<blocks, 256>>>(batch, bias, N);
    }
    final_kernel<<<1, 128>>>(batch, N, Wl, bl, out);
}

// round 10
// speedup vs baseline: 1.2209x; 1.0148x over previous
#include <cuda_runtime.h>
#include <cuda_bf16.h>

// Problem constants (fixed by the reference setup)
#define MAXN 50000
#define MAXE 800000
#define FEAT 128
#define NHEAD 4
#define CDIM 32
#define NGRAPH 64
#define NEG_SLOPE 0.2f
#define SCAN_BS 256

// ---------------- device scratch (no allocations allowed) ----------------
__device__ __align__(256) float g_xp[MAXN * FEAT];        // projected features [N,128] fp32
__device__ __align__(256) __nv_bfloat162 g_xpb[MAXN * (FEAT/2)];  // bf16 copy for gather
__device__ __align__(256) float g_asrc[MAXN * NHEAD];     // per-node src logits [N,4]
__device__ __align__(256) float g_adst[MAXN * NHEAD];     // per-node dst logits [N,4]
__device__ __align__(256) int   g_deg[MAXN];              // in-degree histogram
__device__ __align__(256) int   g_off[MAXN + 1];          // CSR offsets
__device__ __align__(256) int   g_cursor[MAXN];           // CSR fill cursors
__device__ __align__(256) int   g_esrc[MAXE];             // CSR: src node per edge slot
__device__ __align__(256) float g_pooled[NGRAPH * FEAT];  // per-graph feature sums
__device__ __align__(256) int   g_bsum[(MAXN + SCAN_BS - 1) / SCAN_BS];  // block sums
__device__ __align__(256) int   g_bpre[(MAXN + SCAN_BS - 1) / SCAN_BS];  // block prefixes

// ---------------- K0: zero scratch that must start at 0 ----------------
__global__ void zero_kernel(int Nn) {
    int idx = blockIdx.x * blockDim.x + threadIdx.x;
    if (idx < Nn) g_deg[idx] = 0;
    if (idx < NGRAPH * FEAT) g_pooled[idx] = 0.f;
}

// ---------------- K1: xp = x @ W, fused att_src/att_dst dots ----------------
__global__ __launch_bounds__(256) void gemm_att_kernel(
    const float* __restrict__ x, const float* __restrict__ W,
    const float* __restrict__ att_s, const float* __restrict__ att_d, int Nn)
{
    __shared__ float sW[32 * FEAT];     // 16KB: one K-chunk of W (rows k..k+31)
    __shared__ float sx[32 * 129];      // 16.5KB padded x tile
    int tid = threadIdx.x;
    int row0 = blockIdx.x * 32;

    for (int idx = tid; idx < 32 * 32; idx += 256) {
        int r = idx >> 5, c4 = idx & 31;
        float4 v = make_float4(0.f, 0.f, 0.f, 0.f);
        if (row0 + r < Nn) v = ((const float4*)(x + (size_t)(row0 + r) * FEAT))[c4];
        float* p = &sx[r * 129 + c4 * 4];
        p[0] = v.x; p[1] = v.y; p[2] = v.z; p[3] = v.w;
    }

    int cg = tid & 31;            // column group: output cols cg*4 .. cg*4+3
    int rb = (tid >> 5) * 4;      // rows rb .. rb+3
    float a00=0,a01=0,a02=0,a03=0, a10=0,a11=0,a12=0,a13=0;
    float a20=0,a21=0,a22=0,a23=0, a30=0,a31=0,a32=0,a33=0;

    const float4* W4 = (const float4*)W;

    for (int kc = 0; kc < 4; kc++) {
        __syncthreads();
        for (int idx = tid; idx < 32 * 32; idx += 256) {
            float4 wv = W4[kc * (32 * 32) + idx];
            float* p = &sW[idx * 4];
            p[0] = wv.x; p[1] = wv.y; p[2] = wv.z; p[3] = wv.w;
        }
        __syncthreads();

#pragma unroll 8
        for (int kk = 0; kk < 32; kk++) {
            int k = kc * 32 + kk;
            const float* wp = &sW[kk * FEAT + cg * 4];
            float w0 = wp[0], w1 = wp[1], w2 = wp[2], w3 = wp[3];
            float xa = sx[(rb + 0) * 129 + k];
            float xb = sx[(rb + 1) * 129 + k];
            float xc = sx[(rb + 2) * 129 + k];
            float xd = sx[(rb + 3) * 129 + k];
            a00 += xa * w0; a01 += xa * w1; a02 += xa * w2; a03 += xa * w3;
            a10 += xb * w0; a11 += xb * w1; a12 += xb * w2; a13 += xb * w3;
            a20 += xc * w0; a21 += xc * w1; a22 += xc * w2; a23 += xc * w3;
            a30 += xd * w0; a31 += xd * w1; a32 += xd * w2; a33 += xd * w3;
        }
    }

    // write xp fp32 (used by nothing but kept for debug-parity) ... actually
    // only the bf16 copy is consumed downstream for features; fp32 copy feeds
    // nothing anymore EXCEPT we keep it omitted to save bandwidth.
    // -> write only bf16 copy + attention logits.
    {
        int c2 = cg * 2;   // bf162 index of first pair
        if (row0 + rb + 0 < Nn) {
            __nv_bfloat162* o = g_xpb + (size_t)(row0 + rb + 0) * (FEAT/2) + c2;
            o[0] = __floats2bfloat162_rn(a00, a01);
            o[1] = __floats2bfloat162_rn(a02, a03);
        }
        if (row0 + rb + 1 < Nn) {
            __nv_bfloat162* o = g_xpb + (size_t)(row0 + rb + 1) * (FEAT/2) + c2;
            o[0] = __floats2bfloat162_rn(a10, a11);
            o[1] = __floats2bfloat162_rn(a12, a13);
        }
        if (row0 + rb + 2 < Nn) {
            __nv_bfloat162* o = g_xpb + (size_t)(row0 + rb + 2) * (FEAT/2) + c2;
            o[0] = __floats2bfloat162_rn(a20, a21);
            o[1] = __floats2bfloat162_rn(a22, a23);
        }
        if (row0 + rb + 3 < Nn) {
            __nv_bfloat162* o = g_xpb + (size_t)(row0 + rb + 3) * (FEAT/2) + c2;
            o[0] = __floats2bfloat162_rn(a30, a31);
            o[1] = __floats2bfloat162_rn(a32, a33);
        }
    }

    __syncthreads();   // everyone done reading sx in the K loop
    {
        float* p0 = &sx[(rb + 0) * 129 + cg * 4];
        p0[0]=a00; p0[1]=a01; p0[2]=a02; p0[3]=a03;
        float* p1 = &sx[(rb + 1) * 129 + cg * 4];
        p1[0]=a10; p1[1]=a11; p1[2]=a12; p1[3]=a13;
        float* p2 = &sx[(rb + 2) * 129 + cg * 4];
        p2[0]=a20; p2[1]=a21; p2[2]=a22; p2[3]=a23;
        float* p3 = &sx[(rb + 3) * 129 + cg * 4];
        p3[0]=a30; p3[1]=a31; p3[2]=a32; p3[3]=a33;
    }
    __syncthreads();

    // attention logits in full fp32 (exp amplification -> keep precise)
    if (tid < 128) {
        int h = tid >> 5, rr = tid & 31;
        if (row0 + rr < Nn) {
            float ds = 0.f, dd = 0.f;
#pragma unroll
            for (int c = 0; c < CDIM; c++) {
                float v = sx[rr * 129 + h * CDIM + c];
                ds += v * att_s[h * CDIM + c];
                dd += v * att_d[h * CDIM + c];
            }
            g_asrc[(row0 + rr) * NHEAD + h] = ds;
            g_adst[(row0 + rr) * NHEAD + h] = dd;
        }
    }
}

// ---------------- K2: in-degree histogram (edge_index is int32) ----------------
__global__ void hist_kernel(const int* __restrict__ ei, int E) {
    int idx = blockIdx.x * blockDim.x + threadIdx.x;
    if (idx < E) atomicAdd(&g_deg[ei[E + idx]], 1);
}

// ---------------- K3a: per-block degree sums ----------------
__global__ __launch_bounds__(SCAN_BS) void scan_pass1(int Nn) {
    __shared__ int sh[SCAN_BS];
    int i = blockIdx.x * SCAN_BS + threadIdx.x;
    int v = (i < Nn) ? g_deg[i] : 0;
    sh[threadIdx.x] = v;
    __syncthreads();
    for (int d = SCAN_BS / 2; d > 0; d >>= 1) {
        if (threadIdx.x < d) sh[threadIdx.x] += sh[threadIdx.x + d];
        __syncthreads();
    }
    if (threadIdx.x == 0) g_bsum[blockIdx.x] = sh[0];
}

// ---------------- K3b: scan of block sums (nb <= 256) ----------------
__global__ __launch_bounds__(SCAN_BS) void scan_pass2(int nb) {
    __shared__ int sh[SCAN_BS];
    int t = threadIdx.x;
    sh[t] = (t < nb) ? g_bsum[t] : 0;
    __syncthreads();
    for (int d = 1; d < SCAN_BS; d <<= 1) {
        int v = (t >= d) ? sh[t - d] : 0;
        __syncthreads();
        sh[t] += v;
        __syncthreads();
    }
    if (t < nb) g_bpre[t] = (t > 0) ? sh[t - 1] : 0;   // exclusive
}

// ---------------- K3c: per-block exclusive scan + offsets + cursors ----------------
__global__ __launch_bounds__(SCAN_BS) void scan_pass3(int Nn) {
    __shared__ int sh[SCAN_BS];
    int t = threadIdx.x;
    int i = blockIdx.x * SCAN_BS + t;
    int v = (i < Nn) ? g_deg[i] : 0;
    sh[t] = v;
    __syncthreads();
    for (int d = 1; d < SCAN_BS; d <<= 1) {
        int u = (t >= d) ? sh[t - d] : 0;
        __syncthreads();
        sh[t] += u;
        __syncthreads();
    }
    int incl = sh[t];
    int base = g_bpre[blockIdx.x];
    int pre = base + incl - v;          // exclusive prefix
    if (i < Nn) {
        g_off[i] = pre;
        g_cursor[i] = pre;
        if (i == Nn - 1) g_off[Nn] = pre + v;
    }
}

// ---------------- K5: CSR fill (src per slot) ----------------
__global__ void csr_kernel(const int* __restrict__ ei, int E) {
    int idx = blockIdx.x * blockDim.x + threadIdx.x;
    if (idx < E) {
        int d = ei[E + idx];
        int s = ei[idx];
        int pos = atomicAdd(&g_cursor[d], 1);
        g_esrc[pos] = s;
    }
}

// ---------------- K6: fused softmax + aggregate + relu + pool ----------------
// TWO dst nodes per warp (independent chains). Features gathered as bf16
// (8B/lane/row instead of 16B) -> half the L2 gather traffic.
__global__ __launch_bounds__(256) void agg_kernel(
    const int* __restrict__ batch, const float* __restrict__ bias, int Nn)
{
    int warp = (blockIdx.x * blockDim.x + threadIdx.x) >> 5;
    int lane = threadIdx.x & 31;
    int i0 = warp * 2;
    if (i0 >= Nn) return;
    int i1 = i0 + 1;
    bool has1 = (i1 < Nn);
    int h = lane >> 3;           // head of my 4 columns

    // ---- node 0 setup ----
    float adh0 = g_adst[i0 * 4 + h];
    float es0 = g_asrc[i0 * 4 + h] + adh0;
    float wsh0 = __expf(fmaxf(es0, NEG_SLOPE * es0));
    float4 acc0;
    {
        uint2 u = ((const uint2*)(g_xpb + (size_t)i0 * (FEAT/2)))[lane];
        float2 p0 = __bfloat1622float2(*reinterpret_cast<__nv_bfloat162*>(&u.x));
        float2 p1 = __bfloat1622float2(*reinterpret_cast<__nv_bfloat162*>(&u.y));
        acc0 = make_float4(wsh0 * p0.x, wsh0 * p0.y, wsh0 * p1.x, wsh0 * p1.y);
    }
    float s0 = wsh0;

    // ---- node 1 setup (predicated) ----
    float adh1 = 0.f;
    float4 acc1 = make_float4(0.f, 0.f, 0.f, 0.f);
    float s1 = 0.f;
    if (has1) {
        adh1 = g_adst[i1 * 4 + h];
        float es1 = g_asrc[i1 * 4 + h] + adh1;
        float wsh1 = __expf(fmaxf(es1, NEG_SLOPE * es1));
        uint2 u = ((const uint2*)(g_xpb + (size_t)i1 * (FEAT/2)))[lane];
        float2 p0 = __bfloat1622float2(*reinterpret_cast<__nv_bfloat162*>(&u.x));
        float2 p1 = __bfloat1622float2(*reinterpret_cast<__nv_bfloat162*>(&u.y));
        acc1 = make_float4(wsh1 * p0.x, wsh1 * p0.y, wsh1 * p1.x, wsh1 * p1.y);
        s1 = wsh1;
    }

    int beg0 = g_off[i0], end0 = g_off[i0 + 1];
    int beg1 = has1 ? g_off[i1] : 0, end1 = has1 ? g_off[i1 + 1] : 0;
    int len0 = end0 - beg0, len1 = end1 - beg1;
    int L = max(len0, len1);

#pragma unroll 2
    for (int t = 0; t < L; t++) {
        // issue both index loads first (independent chains)
        int sj0 = (t < len0) ? g_esrc[beg0 + t] : 0;
        int sj1 = (t < len1) ? g_esrc[beg1 + t] : 0;
        // chain 0
        if (t < len0) {
            float f = g_asrc[sj0 * 4 + h] + adh0;
            float w = __expf(fmaxf(f, NEG_SLOPE * f));
            s0 += w;
            uint2 u = ((const uint2*)(g_xpb + (size_t)sj0 * (FEAT/2)))[lane];
            float2 p0 = __bfloat1622float2(*reinterpret_cast<__nv_bfloat162*>(&u.x));
            float2 p1 = __bfloat1622float2(*reinterpret_cast<__nv_bfloat162*>(&u.y));
            acc0.x += w * p0.x; acc0.y += w * p0.y; acc0.z += w * p1.x; acc0.w += w * p1.y;
        }
        // chain 1
        if (t < len1) {
            float f = g_asrc[sj1 * 4 + h] + adh1;
            float w = __expf(fmaxf(f, NEG_SLOPE * f));
            s1 += w;
            uint2 u = ((const uint2*)(g_xpb + (size_t)sj1 * (FEAT/2)))[lane];
            float2 p0 = __bfloat1622float2(*reinterpret_cast<__nv_bfloat162*>(&u.x));
            float2 p1 = __bfloat1622float2(*reinterpret_cast<__nv_bfloat162*>(&u.y));
            acc1.x += w * p0.x; acc1.y += w * p0.y; acc1.z += w * p1.x; acc1.w += w * p1.y;
        }
    }

    float4 b4 = ((const float4*)bias)[lane];

    {
        float inv = 1.0f / s0;
        float o0 = fmaxf(acc0.x * inv + b4.x, 0.f);
        float o1 = fmaxf(acc0.y * inv + b4.y, 0.f);
        float o2 = fmaxf(acc0.z * inv + b4.z, 0.f);
        float o3 = fmaxf(acc0.w * inv + b4.w, 0.f);
        int g = batch[i0];
        float* pg = g_pooled + g * FEAT + lane * 4;
        atomicAdd(pg + 0, o0);
        atomicAdd(pg + 1, o1);
        atomicAdd(pg + 2, o2);
        atomicAdd(pg + 3, o3);
    }
    if (has1) {
        float inv = 1.0f / s1;
        float o0 = fmaxf(acc1.x * inv + b4.x, 0.f);
        float o1 = fmaxf(acc1.y * inv + b4.y, 0.f);
        float o2 = fmaxf(acc1.z * inv + b4.z, 0.f);
        float o3 = fmaxf(acc1.w * inv + b4.w, 0.f);
        int g = batch[i1];
        float* pg = g_pooled + g * FEAT + lane * 4;
        atomicAdd(pg + 0, o0);
        atomicAdd(pg + 1, o1);
        atomicAdd(pg + 2, o2);
        atomicAdd(pg + 3, o3);
    }
}

// ---------------- K7: mean + final linear ----------------
__global__ void final_kernel(const int* __restrict__ batch, int Nn,
                             const float* __restrict__ Wl, const float* __restrict__ bl,
                             float* __restrict__ out)
{
    int t = threadIdx.x;
    if (t >= NGRAPH * 2) return;
    int g = t >> 1, o = t & 1;
    int lo = 0, hi = Nn;
    while (lo < hi) { int m = (lo + hi) >> 1; if (batch[m] < g) lo = m + 1; else hi = m; }
    int c0 = lo;
    lo = 0; hi = Nn;
    while (lo < hi) { int m = (lo + hi) >> 1; if (batch[m] < g + 1) lo = m + 1; else hi = m; }
    int cnt = lo - c0;
    float fc = (float)max(cnt, 1);
    float sum = 0.f;
#pragma unroll 4
    for (int k = 0; k < FEAT; k++) sum += g_pooled[g * FEAT + k] * Wl[k * 2 + o];
    out[g * 2 + o] = sum / fc + bl[o];
}

// ---------------- launch ----------------
extern "C" void kernel_launch(void* const* d_in, const int* in_sizes, int n_in,
                              void* d_out, int out_size)
{
    const float* x     = (const float*)d_in[0];
    const int*   ei    = (const int*)d_in[1];     // int32 on the wire
    const int*   batch = (const int*)d_in[2];     // int32 on the wire
    const float* W     = (const float*)d_in[3];
    const float* att_s = (const float*)d_in[4];
    const float* att_d = (const float*)d_in[5];
    const float* bias  = (const float*)d_in[6];
    const float* Wl    = (const float*)d_in[7];
    const float* bl    = (const float*)d_in[8];
    float* out = (float*)d_out;

    int N = in_sizes[0] / FEAT;
    int E = in_sizes[1] / 2;
    int nb = (N + SCAN_BS - 1) / SCAN_BS;

    zero_kernel<<<(N + 255) / 256, 256>>>(N);
    gemm_att_kernel<<<(N + 31) / 32, 256>>>(x, W, att_s, att_d, N);
    hist_kernel<<<(E + 255) / 256, 256>>>(ei, E);
    scan_pass1<<<nb, SCAN_BS>>>(N);
    scan_pass2<<<1, SCAN_BS>>>(nb);
    scan_pass3<<<nb, SCAN_BS>>>(N);
    csr_kernel<<<(E + 255) / 256, 256>>>(ei, E);
    {
        int nwarps = (N + 1) / 2;
        long long threads = (long long)nwarps * 32;
        int blocks = (int)((threads + 255) / 256);
        agg_kernel<<<blocks, 256>>>(batch, bias, N);
    }
    final_kernel<<<1, 128>>>(batch, N, Wl, bl, out);
}

// round 11
// speedup vs baseline: 1.8432x; 1.5097x over previous
#include <cuda_runtime.h>
#include <cuda_bf16.h>

// Problem constants (fixed by the reference setup)
#define MAXN 50000
#define MAXE 800000
#define FEAT 128
#define NHEAD 4
#define CDIM 32
#define NGRAPH 64
#define NEG_SLOPE 0.2f
#define SCAN_BS 256

// ---------------- device scratch (no allocations allowed) ----------------
__device__ __align__(256) __nv_bfloat162 g_xpb[MAXN * (FEAT/2)];  // bf16 features for gather
__device__ __align__(256) float g_asrc[MAXN * NHEAD];     // per-node src logits [N,4]
__device__ __align__(256) float g_adst[MAXN * NHEAD];     // per-node dst logits [N,4]
__device__ __align__(256) float g_ew[MAXE * NHEAD];       // per-edge softmax numerators
__device__ __align__(256) int   g_deg[MAXN];              // in-degree histogram
__device__ __align__(256) int   g_off[MAXN + 1];          // CSR offsets
__device__ __align__(256) int   g_cursor[MAXN];           // CSR fill cursors
__device__ __align__(256) int   g_esrc[MAXE];             // CSR: src node per edge slot
__device__ __align__(256) float g_pooled[NGRAPH * FEAT];  // per-graph feature sums
__device__ __align__(256) int   g_bsum[(MAXN + SCAN_BS - 1) / SCAN_BS];  // block sums
__device__ __align__(256) int   g_bpre[(MAXN + SCAN_BS - 1) / SCAN_BS];  // block prefixes

// ---------------- K0: zero scratch that must start at 0 ----------------
__global__ void zero_kernel(int Nn) {
    int idx = blockIdx.x * blockDim.x + threadIdx.x;
    if (idx < Nn) g_deg[idx] = 0;
    if (idx < NGRAPH * FEAT) g_pooled[idx] = 0.f;
}

// ---------------- K1: xp = x @ W (bf16 out), fused att dots ----------------
__global__ __launch_bounds__(256) void gemm_att_kernel(
    const float* __restrict__ x, const float* __restrict__ W,
    const float* __restrict__ att_s, const float* __restrict__ att_d, int Nn)
{
    __shared__ float sW[32 * FEAT];     // 16KB: one K-chunk of W (rows k..k+31)
    __shared__ float sx[32 * 129];      // 16.5KB padded x tile
    int tid = threadIdx.x;
    int row0 = blockIdx.x * 32;

    for (int idx = tid; idx < 32 * 32; idx += 256) {
        int r = idx >> 5, c4 = idx & 31;
        float4 v = make_float4(0.f, 0.f, 0.f, 0.f);
        if (row0 + r < Nn) v = ((const float4*)(x + (size_t)(row0 + r) * FEAT))[c4];
        float* p = &sx[r * 129 + c4 * 4];
        p[0] = v.x; p[1] = v.y; p[2] = v.z; p[3] = v.w;
    }

    int cg = tid & 31;            // column group: output cols cg*4 .. cg*4+3
    int rb = (tid >> 5) * 4;      // rows rb .. rb+3
    float a00=0,a01=0,a02=0,a03=0, a10=0,a11=0,a12=0,a13=0;
    float a20=0,a21=0,a22=0,a23=0, a30=0,a31=0,a32=0,a33=0;

    const float4* W4 = (const float4*)W;

    for (int kc = 0; kc < 4; kc++) {
        __syncthreads();
        for (int idx = tid; idx < 32 * 32; idx += 256) {
            float4 wv = W4[kc * (32 * 32) + idx];
            float* p = &sW[idx * 4];
            p[0] = wv.x; p[1] = wv.y; p[2] = wv.z; p[3] = wv.w;
        }
        __syncthreads();

#pragma unroll 8
        for (int kk = 0; kk < 32; kk++) {
            int k = kc * 32 + kk;
            const float* wp = &sW[kk * FEAT + cg * 4];
            float w0 = wp[0], w1 = wp[1], w2 = wp[2], w3 = wp[3];
            float xa = sx[(rb + 0) * 129 + k];
            float xb = sx[(rb + 1) * 129 + k];
            float xc = sx[(rb + 2) * 129 + k];
            float xd = sx[(rb + 3) * 129 + k];
            a00 += xa * w0; a01 += xa * w1; a02 += xa * w2; a03 += xa * w3;
            a10 += xb * w0; a11 += xb * w1; a12 += xb * w2; a13 += xb * w3;
            a20 += xc * w0; a21 += xc * w1; a22 += xc * w2; a23 += xc * w3;
            a30 += xd * w0; a31 += xd * w1; a32 += xd * w2; a33 += xd * w3;
        }
    }

    // write bf16 feature copy (only consumer of features downstream)
    {
        int c2 = cg * 2;   // bf162 index of first pair
        if (row0 + rb + 0 < Nn) {
            __nv_bfloat162* o = g_xpb + (size_t)(row0 + rb + 0) * (FEAT/2) + c2;
            o[0] = __floats2bfloat162_rn(a00, a01);
            o[1] = __floats2bfloat162_rn(a02, a03);
        }
        if (row0 + rb + 1 < Nn) {
            __nv_bfloat162* o = g_xpb + (size_t)(row0 + rb + 1) * (FEAT/2) + c2;
            o[0] = __floats2bfloat162_rn(a10, a11);
            o[1] = __floats2bfloat162_rn(a12, a13);
        }
        if (row0 + rb + 2 < Nn) {
            __nv_bfloat162* o = g_xpb + (size_t)(row0 + rb + 2) * (FEAT/2) + c2;
            o[0] = __floats2bfloat162_rn(a20, a21);
            o[1] = __floats2bfloat162_rn(a22, a23);
        }
        if (row0 + rb + 3 < Nn) {
            __nv_bfloat162* o = g_xpb + (size_t)(row0 + rb + 3) * (FEAT/2) + c2;
            o[0] = __floats2bfloat162_rn(a30, a31);
            o[1] = __floats2bfloat162_rn(a32, a33);
        }
    }

    __syncthreads();   // everyone done reading sx in the K loop
    {
        float* p0 = &sx[(rb + 0) * 129 + cg * 4];
        p0[0]=a00; p0[1]=a01; p0[2]=a02; p0[3]=a03;
        float* p1 = &sx[(rb + 1) * 129 + cg * 4];
        p1[0]=a10; p1[1]=a11; p1[2]=a12; p1[3]=a13;
        float* p2 = &sx[(rb + 2) * 129 + cg * 4];
        p2[0]=a20; p2[1]=a21; p2[2]=a22; p2[3]=a23;
        float* p3 = &sx[(rb + 3) * 129 + cg * 4];
        p3[0]=a30; p3[1]=a31; p3[2]=a32; p3[3]=a33;
    }
    __syncthreads();

    // attention logits in full fp32 (exp amplification -> keep precise)
    if (tid < 128) {
        int h = tid >> 5, rr = tid & 31;
        if (row0 + rr < Nn) {
            float ds = 0.f, dd = 0.f;
#pragma unroll
            for (int c = 0; c < CDIM; c++) {
                float v = sx[rr * 129 + h * CDIM + c];
                ds += v * att_s[h * CDIM + c];
                dd += v * att_d[h * CDIM + c];
            }
            g_asrc[(row0 + rr) * NHEAD + h] = ds;
            g_adst[(row0 + rr) * NHEAD + h] = dd;
        }
    }
}

// ---------------- K2: in-degree histogram (edge_index is int32) ----------------
__global__ void hist_kernel(const int* __restrict__ ei, int E) {
    int idx = blockIdx.x * blockDim.x + threadIdx.x;
    if (idx < E) atomicAdd(&g_deg[ei[E + idx]], 1);
}

// ---------------- K3a: per-block degree sums ----------------
__global__ __launch_bounds__(SCAN_BS) void scan_pass1(int Nn) {
    __shared__ int sh[SCAN_BS];
    int i = blockIdx.x * SCAN_BS + threadIdx.x;
    int v = (i < Nn) ? g_deg[i] : 0;
    sh[threadIdx.x] = v;
    __syncthreads();
    for (int d = SCAN_BS / 2; d > 0; d >>= 1) {
        if (threadIdx.x < d) sh[threadIdx.x] += sh[threadIdx.x + d];
        __syncthreads();
    }
    if (threadIdx.x == 0) g_bsum[blockIdx.x] = sh[0];
}

// ---------------- K3b: scan of block sums (nb <= 256) ----------------
__global__ __launch_bounds__(SCAN_BS) void scan_pass2(int nb) {
    __shared__ int sh[SCAN_BS];
    int t = threadIdx.x;
    sh[t] = (t < nb) ? g_bsum[t] : 0;
    __syncthreads();
    for (int d = 1; d < SCAN_BS; d <<= 1) {
        int v = (t >= d) ? sh[t - d] : 0;
        __syncthreads();
        sh[t] += v;
        __syncthreads();
    }
    if (t < nb) g_bpre[t] = (t > 0) ? sh[t - 1] : 0;   // exclusive
}

// ---------------- K3c: per-block exclusive scan + offsets + cursors ----------------
__global__ __launch_bounds__(SCAN_BS) void scan_pass3(int Nn) {
    __shared__ int sh[SCAN_BS];
    int t = threadIdx.x;
    int i = blockIdx.x * SCAN_BS + t;
    int v = (i < Nn) ? g_deg[i] : 0;
    sh[t] = v;
    __syncthreads();
    for (int d = 1; d < SCAN_BS; d <<= 1) {
        int u = (t >= d) ? sh[t - d] : 0;
        __syncthreads();
        sh[t] += u;
        __syncthreads();
    }
    int incl = sh[t];
    int base = g_bpre[blockIdx.x];
    int pre = base + incl - v;          // exclusive prefix
    if (i < Nn) {
        g_off[i] = pre;
        g_cursor[i] = pre;
        if (i == Nn - 1) g_off[Nn] = pre + v;
    }
}

// ---------------- K5: CSR fill + edge-weight precompute ----------------
// One thread per edge: slot assignment AND the 4 per-head softmax numerators.
// E-parallel with huge MLP, so the random asrc/adst gathers are cheap here —
// and they vanish from agg_kernel's critical chain.
__global__ void csr_kernel(const int* __restrict__ ei, int E) {
    int idx = blockIdx.x * blockDim.x + threadIdx.x;
    if (idx < E) {
        int d = ei[E + idx];
        int s = ei[idx];
        int pos = atomicAdd(&g_cursor[d], 1);
        g_esrc[pos] = s;
        float4 as = *(const float4*)(g_asrc + s * 4);
        float4 ad = *(const float4*)(g_adst + d * 4);
        float f0 = as.x + ad.x, f1 = as.y + ad.y, f2 = as.z + ad.z, f3 = as.w + ad.w;
        float4 w;
        w.x = __expf(fmaxf(f0, NEG_SLOPE * f0));
        w.y = __expf(fmaxf(f1, NEG_SLOPE * f1));
        w.z = __expf(fmaxf(f2, NEG_SLOPE * f2));
        w.w = __expf(fmaxf(f3, NEG_SLOPE * f3));
        *(float4*)(g_ew + (size_t)pos * 4) = w;
    }
}

// ---------------- K6: aggregate + relu + smem-pooled reduction ----------------
// 8 warps/block, 2 dst nodes per warp -> 16 consecutive nodes per block.
// Weights read LINEARLY from g_ew (no dependent random load); only the
// feature gather depends on esrc. Pooling goes through shared memory
// (batch sorted => block spans <=2 graphs) cutting global atomics ~8x.
__global__ __launch_bounds__(256) void agg_kernel(
    const int* __restrict__ batch, const float* __restrict__ bias, int Nn)
{
    __shared__ float spool[2][FEAT];
    int tid = threadIdx.x;
    int wIn = tid >> 5;
    int lane = tid & 31;
    int warp = blockIdx.x * 8 + wIn;
    int i0 = warp * 2;
    int i1 = i0 + 1;
    bool has0 = (i0 < Nn);
    bool has1 = (i1 < Nn);
    int h = lane >> 3;           // head of my 4 columns

    // init smem pool
    for (int idx = tid; idx < 2 * FEAT; idx += 256) ((float*)spool)[idx] = 0.f;

    int nodeBase = blockIdx.x * 16;
    int gFirst = 0, gLast = 0;
    bool anyNode = (nodeBase < Nn);
    if (anyNode) {
        gFirst = batch[nodeBase];
        gLast  = batch[min(nodeBase + 15, Nn - 1)];
    }
    bool smemOK = anyNode && (gLast - gFirst <= 1);
    __syncthreads();

    float4 acc0 = make_float4(0.f, 0.f, 0.f, 0.f);
    float4 acc1 = make_float4(0.f, 0.f, 0.f, 0.f);
    float s0 = 0.f, s1 = 0.f;

    if (has0) {
        float adh = g_adst[i0 * 4 + h];
        float es = g_asrc[i0 * 4 + h] + adh;
        float ws = __expf(fmaxf(es, NEG_SLOPE * es));
        uint2 u = ((const uint2*)(g_xpb + (size_t)i0 * (FEAT/2)))[lane];
        float2 p0 = __bfloat1622float2(*reinterpret_cast<__nv_bfloat162*>(&u.x));
        float2 p1 = __bfloat1622float2(*reinterpret_cast<__nv_bfloat162*>(&u.y));
        acc0 = make_float4(ws * p0.x, ws * p0.y, ws * p1.x, ws * p1.y);
        s0 = ws;
    }
    if (has1) {
        float adh = g_adst[i1 * 4 + h];
        float es = g_asrc[i1 * 4 + h] + adh;
        float ws = __expf(fmaxf(es, NEG_SLOPE * es));
        uint2 u = ((const uint2*)(g_xpb + (size_t)i1 * (FEAT/2)))[lane];
        float2 p0 = __bfloat1622float2(*reinterpret_cast<__nv_bfloat162*>(&u.x));
        float2 p1 = __bfloat1622float2(*reinterpret_cast<__nv_bfloat162*>(&u.y));
        acc1 = make_float4(ws * p0.x, ws * p0.y, ws * p1.x, ws * p1.y);
        s1 = ws;
    }

    int beg0 = has0 ? g_off[i0] : 0, end0 = has0 ? g_off[i0 + 1] : 0;
    int beg1 = has1 ? g_off[i1] : 0, end1 = has1 ? g_off[i1 + 1] : 0;
    int len0 = end0 - beg0, len1 = end1 - beg1;
    int L = max(len0, len1);

#pragma unroll 2
    for (int t = 0; t < L; t++) {
        int sj0 = (t < len0) ? g_esrc[beg0 + t] : 0;
        int sj1 = (t < len1) ? g_esrc[beg1 + t] : 0;
        if (t < len0) {
            float w = g_ew[(size_t)(beg0 + t) * 4 + h];   // linear load
            s0 += w;
            uint2 u = ((const uint2*)(g_xpb + (size_t)sj0 * (FEAT/2)))[lane];
            float2 p0 = __bfloat1622float2(*reinterpret_cast<__nv_bfloat162*>(&u.x));
            float2 p1 = __bfloat1622float2(*reinterpret_cast<__nv_bfloat162*>(&u.y));
            acc0.x += w * p0.x; acc0.y += w * p0.y; acc0.z += w * p1.x; acc0.w += w * p1.y;
        }
        if (t < len1) {
            float w = g_ew[(size_t)(beg1 + t) * 4 + h];   // linear load
            s1 += w;
            uint2 u = ((const uint2*)(g_xpb + (size_t)sj1 * (FEAT/2)))[lane];
            float2 p0 = __bfloat1622float2(*reinterpret_cast<__nv_bfloat162*>(&u.x));
            float2 p1 = __bfloat1622float2(*reinterpret_cast<__nv_bfloat162*>(&u.y));
            acc1.x += w * p0.x; acc1.y += w * p0.y; acc1.z += w * p1.x; acc1.w += w * p1.y;
        }
    }

    float4 b4 = ((const float4*)bias)[lane];

    if (has0) {
        float inv = 1.0f / s0;
        float o0 = fmaxf(acc0.x * inv + b4.x, 0.f);
        float o1 = fmaxf(acc0.y * inv + b4.y, 0.f);
        float o2 = fmaxf(acc0.z * inv + b4.z, 0.f);
        float o3 = fmaxf(acc0.w * inv + b4.w, 0.f);
        int g = batch[i0];
        if (smemOK) {
            float* sp = spool[g - gFirst] + lane * 4;
            atomicAdd(sp + 0, o0); atomicAdd(sp + 1, o1);
            atomicAdd(sp + 2, o2); atomicAdd(sp + 3, o3);
        } else {
            float* pg = g_pooled + g * FEAT + lane * 4;
            atomicAdd(pg + 0, o0); atomicAdd(pg + 1, o1);
            atomicAdd(pg + 2, o2); atomicAdd(pg + 3, o3);
        }
    }
    if (has1) {
        float inv = 1.0f / s1;
        float o0 = fmaxf(acc1.x * inv + b4.x, 0.f);
        float o1 = fmaxf(acc1.y * inv + b4.y, 0.f);
        float o2 = fmaxf(acc1.z * inv + b4.z, 0.f);
        float o3 = fmaxf(acc1.w * inv + b4.w, 0.f);
        int g = batch[i1];
        if (smemOK) {
            float* sp = spool[g - gFirst] + lane * 4;
            atomicAdd(sp + 0, o0); atomicAdd(sp + 1, o1);
            atomicAdd(sp + 2, o2); atomicAdd(sp + 3, o3);
        } else {
            float* pg = g_pooled + g * FEAT + lane * 4;
            atomicAdd(pg + 0, o0); atomicAdd(pg + 1, o1);
            atomicAdd(pg + 2, o2); atomicAdd(pg + 3, o3);
        }
    }

    __syncthreads();
    if (smemOK) {
        for (int idx = tid; idx < 2 * FEAT; idx += 256) {
            int bank = idx >> 7, c = idx & 127;
            float v = ((float*)spool)[idx];
            int g = gFirst + bank;
            if (v != 0.f && g < NGRAPH)
                atomicAdd(&g_pooled[g * FEAT + c], v);
        }
    }
}

// ---------------- K7: mean + final linear ----------------
__global__ void final_kernel(const int* __restrict__ batch, int Nn,
                             const float* __restrict__ Wl, const float* __restrict__ bl,
                             float* __restrict__ out)
{
    int t = threadIdx.x;
    if (t >= NGRAPH * 2) return;
    int g = t >> 1, o = t & 1;
    int lo = 0, hi = Nn;
    while (lo < hi) { int m = (lo + hi) >> 1; if (batch[m] < g) lo = m + 1; else hi = m; }
    int c0 = lo;
    lo = 0; hi = Nn;
    while (lo < hi) { int m = (lo + hi) >> 1; if (batch[m] < g + 1) lo = m + 1; else hi = m; }
    int cnt = lo - c0;
    float fc = (float)max(cnt, 1);
    float sum = 0.f;
#pragma unroll 4
    for (int k = 0; k < FEAT; k++) sum += g_pooled[g * FEAT + k] * Wl[k * 2 + o];
    out[g * 2 + o] = sum / fc + bl[o];
}

// ---------------- launch ----------------
extern "C" void kernel_launch(void* const* d_in, const int* in_sizes, int n_in,
                              void* d_out, int out_size)
{
    const float* x     = (const float*)d_in[0];
    const int*   ei    = (const int*)d_in[1];     // int32 on the wire
    const int*   batch = (const int*)d_in[2];     // int32 on the wire
    const float* W     = (const float*)d_in[3];
    const float* att_s = (const float*)d_in[4];
    const float* att_d = (const float*)d_in[5];
    const float* bias  = (const float*)d_in[6];
    const float* Wl    = (const float*)d_in[7];
    const float* bl    = (const float*)d_in[8];
    float* out = (float*)d_out;

    int N = in_sizes[0] / FEAT;
    int E = in_sizes[1] / 2;
    int nb = (N + SCAN_BS - 1) / SCAN_BS;

    zero_kernel<<<(N + 255) / 256, 256>>>(N);
    gemm_att_kernel<<<(N + 31) / 32, 256>>>(x, W, att_s, att_d, N);
    hist_kernel<<<(E + 255) / 256, 256>>>(ei, E);
    scan_pass1<<<nb, SCAN_BS>>>(N);
    scan_pass2<<<1, SCAN_BS>>>(nb);
    scan_pass3<<<nb, SCAN_BS>>>(N);
    csr_kernel<<<(E + 255) / 256, 256>>>(ei, E);
    {
        int nblocks = (N + 15) / 16;    // 16 nodes per block (8 warps x 2)
        agg_kernel<<<nblocks, 256>>>(batch, bias, N);
    }
    final_kernel<<<1, 128>>>(batch, N, Wl, bl, out);
}

// round 12
// speedup vs baseline: 2.0082x; 1.0895x over previous
#include <cuda_runtime.h>
#include <cuda_bf16.h>
#include <mma.h>
using namespace nvcuda;

// Problem constants (fixed by the reference setup)
#define MAXN 50000
#define MAXE 800000
#define FEAT 128
#define NHEAD 4
#define CDIM 32
#define NGRAPH 64
#define NEG_SLOPE 0.2f
#define SCAN_BS 256

// ---------------- device scratch (no allocations allowed) ----------------
__device__ __align__(256) __nv_bfloat162 g_xpb[MAXN * (FEAT/2)];  // bf16 features for gather
__device__ __align__(256) float g_asrc[MAXN * NHEAD];     // per-node src logits [N,4]
__device__ __align__(256) float g_adst[MAXN * NHEAD];     // per-node dst logits [N,4]
__device__ __align__(256) float g_ew[MAXE * NHEAD];       // per-edge softmax numerators
__device__ __align__(256) int   g_deg[MAXN];              // in-degree histogram
__device__ __align__(256) int   g_off[MAXN + 1];          // CSR offsets
__device__ __align__(256) int   g_cursor[MAXN];           // CSR fill cursors
__device__ __align__(256) int   g_esrc[MAXE];             // CSR: src node per edge slot
__device__ __align__(256) float g_pooled[NGRAPH * FEAT];  // per-graph feature sums
__device__ __align__(256) int   g_bsum[(MAXN + SCAN_BS - 1) / SCAN_BS];  // block sums
__device__ __align__(256) int   g_bpre[(MAXN + SCAN_BS - 1) / SCAN_BS];  // block prefixes

// ---------------- K0: zero scratch that must start at 0 ----------------
__global__ void zero_kernel(int Nn) {
    int idx = blockIdx.x * blockDim.x + threadIdx.x;
    if (idx < Nn) g_deg[idx] = 0;
    if (idx < NGRAPH * FEAT) g_pooled[idx] = 0.f;
}

// ---------------- K1: xp = x @ W via tf32 tensor cores, fused att dots ----------
// Block: 256 threads (8 warps), 64 rows. Warp grid 2x4: warp covers 32x32
// output (2x2 m16n16k8 fragments). x staged zero-padded in shared (ld=132);
// W fragments from global (L2-hot). Accumulators stored back into the same
// shared buffer for the bf16-write + attention epilogue.
__global__ __launch_bounds__(256) void gemm_att_kernel(
    const float* __restrict__ x, const float* __restrict__ W,
    const float* __restrict__ att_s, const float* __restrict__ att_d, int Nn)
{
    __shared__ __align__(16) float sT[64 * 132];   // 33.8KB: x tile, then output tile
    int tid = threadIdx.x;
    int warp = tid >> 5;
    int row0 = blockIdx.x * 64;

    // stage x tile (zero-padded rows beyond Nn)
    for (int idx = tid; idx < 64 * 32; idx += 256) {
        int r = idx >> 5, c4 = idx & 31;
        float4 v = make_float4(0.f, 0.f, 0.f, 0.f);
        if (row0 + r < Nn) v = ((const float4*)(x + (size_t)(row0 + r) * FEAT))[c4];
        ((float4*)(sT + r * 132))[c4] = v;
    }
    __syncthreads();

    int rt = warp >> 2;      // 0..1 : rows rt*32 .. rt*32+31
    int ct = warp & 3;       // 0..3 : cols ct*32 .. ct*32+31

    wmma::fragment<wmma::accumulator, 16, 16, 8, float> acc[2][2];
#pragma unroll
    for (int i = 0; i < 2; i++)
#pragma unroll
        for (int j = 0; j < 2; j++) wmma::fill_fragment(acc[i][j], 0.0f);

    wmma::fragment<wmma::matrix_a, 16, 16, 8, wmma::precision::tf32, wmma::row_major> fa[2];
    wmma::fragment<wmma::matrix_b, 16, 16, 8, wmma::precision::tf32, wmma::row_major> fb[2];

    for (int k0 = 0; k0 < FEAT; k0 += 8) {
#pragma unroll
        for (int i = 0; i < 2; i++) {
            wmma::load_matrix_sync(fa[i], sT + (rt * 32 + i * 16) * 132 + k0, 132);
#pragma unroll
            for (int t = 0; t < fa[i].num_elements; t++)
                fa[i].x[t] = wmma::__float_to_tf32(fa[i].x[t]);
        }
#pragma unroll
        for (int j = 0; j < 2; j++) {
            wmma::load_matrix_sync(fb[j], W + (size_t)k0 * FEAT + ct * 32 + j * 16, FEAT);
#pragma unroll
            for (int t = 0; t < fb[j].num_elements; t++)
                fb[j].x[t] = wmma::__float_to_tf32(fb[j].x[t]);
        }
#pragma unroll
        for (int i = 0; i < 2; i++)
#pragma unroll
            for (int j = 0; j < 2; j++)
                wmma::mma_sync(acc[i][j], fa[i], fb[j], acc[i][j]);
    }
    __syncthreads();   // all x reads complete before overwriting sT
#pragma unroll
    for (int i = 0; i < 2; i++)
#pragma unroll
        for (int j = 0; j < 2; j++)
            wmma::store_matrix_sync(sT + (rt * 32 + i * 16) * 132 + ct * 32 + j * 16,
                                    acc[i][j], 132, wmma::mem_row_major);
    __syncthreads();

    // bf16 feature write (only consumer of features downstream)
    for (int idx = tid; idx < 64 * 64; idx += 256) {
        int r = idx >> 6, c2 = idx & 63;
        if (row0 + r < Nn) {
            float lo = sT[r * 132 + c2 * 2];
            float hi = sT[r * 132 + c2 * 2 + 1];
            g_xpb[(size_t)(row0 + r) * (FEAT/2) + c2] = __floats2bfloat162_rn(lo, hi);
        }
    }

    // attention logits in fp32: thread = (row rr, head h)
    {
        int rr = tid >> 2, h = tid & 3;
        if (row0 + rr < Nn) {
            float ds = 0.f, dd = 0.f;
#pragma unroll
            for (int c = 0; c < CDIM; c++) {
                float v = sT[rr * 132 + h * CDIM + c];
                ds += v * att_s[h * CDIM + c];
                dd += v * att_d[h * CDIM + c];
            }
            g_asrc[(row0 + rr) * NHEAD + h] = ds;
            g_adst[(row0 + rr) * NHEAD + h] = dd;
        }
    }
}

// ---------------- K2: in-degree histogram (edge_index is int32) ----------------
__global__ void hist_kernel(const int* __restrict__ ei, int E) {
    int idx = blockIdx.x * blockDim.x + threadIdx.x;
    if (idx < E) atomicAdd(&g_deg[ei[E + idx]], 1);
}

// ---------------- K3a: per-block degree sums ----------------
__global__ __launch_bounds__(SCAN_BS) void scan_pass1(int Nn) {
    __shared__ int sh[SCAN_BS];
    int i = blockIdx.x * SCAN_BS + threadIdx.x;
    int v = (i < Nn) ? g_deg[i] : 0;
    sh[threadIdx.x] = v;
    __syncthreads();
    for (int d = SCAN_BS / 2; d > 0; d >>= 1) {
        if (threadIdx.x < d) sh[threadIdx.x] += sh[threadIdx.x + d];
        __syncthreads();
    }
    if (threadIdx.x == 0) g_bsum[blockIdx.x] = sh[0];
}

// ---------------- K3b: scan of block sums (nb <= 256) ----------------
__global__ __launch_bounds__(SCAN_BS) void scan_pass2(int nb) {
    __shared__ int sh[SCAN_BS];
    int t = threadIdx.x;
    sh[t] = (t < nb) ? g_bsum[t] : 0;
    __syncthreads();
    for (int d = 1; d < SCAN_BS; d <<= 1) {
        int v = (t >= d) ? sh[t - d] : 0;
        __syncthreads();
        sh[t] += v;
        __syncthreads();
    }
    if (t < nb) g_bpre[t] = (t > 0) ? sh[t - 1] : 0;   // exclusive
}

// ---------------- K3c: per-block exclusive scan + offsets + cursors ----------------
__global__ __launch_bounds__(SCAN_BS) void scan_pass3(int Nn) {
    __shared__ int sh[SCAN_BS];
    int t = threadIdx.x;
    int i = blockIdx.x * SCAN_BS + t;
    int v = (i < Nn) ? g_deg[i] : 0;
    sh[t] = v;
    __syncthreads();
    for (int d = 1; d < SCAN_BS; d <<= 1) {
        int u = (t >= d) ? sh[t - d] : 0;
        __syncthreads();
        sh[t] += u;
        __syncthreads();
    }
    int incl = sh[t];
    int base = g_bpre[blockIdx.x];
    int pre = base + incl - v;          // exclusive prefix
    if (i < Nn) {
        g_off[i] = pre;
        g_cursor[i] = pre;
        if (i == Nn - 1) g_off[Nn] = pre + v;
    }
}

// ---------------- K5: CSR fill + edge-weight precompute ----------------
__global__ void csr_kernel(const int* __restrict__ ei, int E) {
    int idx = blockIdx.x * blockDim.x + threadIdx.x;
    if (idx < E) {
        int d = ei[E + idx];
        int s = ei[idx];
        int pos = atomicAdd(&g_cursor[d], 1);
        g_esrc[pos] = s;
        float4 as = *(const float4*)(g_asrc + s * 4);
        float4 ad = *(const float4*)(g_adst + d * 4);
        float f0 = as.x + ad.x, f1 = as.y + ad.y, f2 = as.z + ad.z, f3 = as.w + ad.w;
        float4 w;
        w.x = __expf(fmaxf(f0, NEG_SLOPE * f0));
        w.y = __expf(fmaxf(f1, NEG_SLOPE * f1));
        w.z = __expf(fmaxf(f2, NEG_SLOPE * f2));
        w.w = __expf(fmaxf(f3, NEG_SLOPE * f3));
        *(float4*)(g_ew + (size_t)pos * 4) = w;
    }
}

// ---------------- K6: aggregate + relu + smem-pooled reduction ----------------
__global__ __launch_bounds__(256) void agg_kernel(
    const int* __restrict__ batch, const float* __restrict__ bias, int Nn)
{
    __shared__ float spool[2][FEAT];
    int tid = threadIdx.x;
    int wIn = tid >> 5;
    int lane = tid & 31;
    int warp = blockIdx.x * 8 + wIn;
    int i0 = warp * 2;
    int i1 = i0 + 1;
    bool has0 = (i0 < Nn);
    bool has1 = (i1 < Nn);
    int h = lane >> 3;           // head of my 4 columns

    for (int idx = tid; idx < 2 * FEAT; idx += 256) ((float*)spool)[idx] = 0.f;

    int nodeBase = blockIdx.x * 16;
    int gFirst = 0, gLast = 0;
    bool anyNode = (nodeBase < Nn);
    if (anyNode) {
        gFirst = batch[nodeBase];
        gLast  = batch[min(nodeBase + 15, Nn - 1)];
    }
    bool smemOK = anyNode && (gLast - gFirst <= 1);
    __syncthreads();

    float4 acc0 = make_float4(0.f, 0.f, 0.f, 0.f);
    float4 acc1 = make_float4(0.f, 0.f, 0.f, 0.f);
    float s0 = 0.f, s1 = 0.f;

    if (has0) {
        float adh = g_adst[i0 * 4 + h];
        float es = g_asrc[i0 * 4 + h] + adh;
        float ws = __expf(fmaxf(es, NEG_SLOPE * es));
        uint2 u = ((const uint2*)(g_xpb + (size_t)i0 * (FEAT/2)))[lane];
        float2 p0 = __bfloat1622float2(*reinterpret_cast<__nv_bfloat162*>(&u.x));
        float2 p1 = __bfloat1622float2(*reinterpret_cast<__nv_bfloat162*>(&u.y));
        acc0 = make_float4(ws * p0.x, ws * p0.y, ws * p1.x, ws * p1.y);
        s0 = ws;
    }
    if (has1) {
        float adh = g_adst[i1 * 4 + h];
        float es = g_asrc[i1 * 4 + h] + adh;
        float ws = __expf(fmaxf(es, NEG_SLOPE * es));
        uint2 u = ((const uint2*)(g_xpb + (size_t)i1 * (FEAT/2)))[lane];
        float2 p0 = __bfloat1622float2(*reinterpret_cast<__nv_bfloat162*>(&u.x));
        float2 p1 = __bfloat1622float2(*reinterpret_cast<__nv_bfloat162*>(&u.y));
        acc1 = make_float4(ws * p0.x, ws * p0.y, ws * p1.x, ws * p1.y);
        s1 = ws;
    }

    int beg0 = has0 ? g_off[i0] : 0, end0 = has0 ? g_off[i0 + 1] : 0;
    int beg1 = has1 ? g_off[i1] : 0, end1 = has1 ? g_off[i1 + 1] : 0;
    int len0 = end0 - beg0, len1 = end1 - beg1;
    int L = max(len0, len1);

#pragma unroll 2
    for (int t = 0; t < L; t++) {
        int sj0 = (t < len0) ? g_esrc[beg0 + t] : 0;
        int sj1 = (t < len1) ? g_esrc[beg1 + t] : 0;
        if (t < len0) {
            float w = g_ew[(size_t)(beg0 + t) * 4 + h];   // linear load
            s0 += w;
            uint2 u = ((const uint2*)(g_xpb + (size_t)sj0 * (FEAT/2)))[lane];
            float2 p0 = __bfloat1622float2(*reinterpret_cast<__nv_bfloat162*>(&u.x));
            float2 p1 = __bfloat1622float2(*reinterpret_cast<__nv_bfloat162*>(&u.y));
            acc0.x += w * p0.x; acc0.y += w * p0.y; acc0.z += w * p1.x; acc0.w += w * p1.y;
        }
        if (t < len1) {
            float w = g_ew[(size_t)(beg1 + t) * 4 + h];   // linear load
            s1 += w;
            uint2 u = ((const uint2*)(g_xpb + (size_t)sj1 * (FEAT/2)))[lane];
            float2 p0 = __bfloat1622float2(*reinterpret_cast<__nv_bfloat162*>(&u.x));
            float2 p1 = __bfloat1622float2(*reinterpret_cast<__nv_bfloat162*>(&u.y));
            acc1.x += w * p0.x; acc1.y += w * p0.y; acc1.z += w * p1.x; acc1.w += w * p1.y;
        }
    }

    float4 b4 = ((const float4*)bias)[lane];

    if (has0) {
        float inv = 1.0f / s0;
        float o0 = fmaxf(acc0.x * inv + b4.x, 0.f);
        float o1 = fmaxf(acc0.y * inv + b4.y, 0.f);
        float o2 = fmaxf(acc0.z * inv + b4.z, 0.f);
        float o3 = fmaxf(acc0.w * inv + b4.w, 0.f);
        int g = batch[i0];
        if (smemOK) {
            float* sp = spool[g - gFirst] + lane * 4;
            atomicAdd(sp + 0, o0); atomicAdd(sp + 1, o1);
            atomicAdd(sp + 2, o2); atomicAdd(sp + 3, o3);
        } else {
            float* pg = g_pooled + g * FEAT + lane * 4;
            atomicAdd(pg + 0, o0); atomicAdd(pg + 1, o1);
            atomicAdd(pg + 2, o2); atomicAdd(pg + 3, o3);
        }
    }
    if (has1) {
        float inv = 1.0f / s1;
        float o0 = fmaxf(acc1.x * inv + b4.x, 0.f);
        float o1 = fmaxf(acc1.y * inv + b4.y, 0.f);
        float o2 = fmaxf(acc1.z * inv + b4.z, 0.f);
        float o3 = fmaxf(acc1.w * inv + b4.w, 0.f);
        int g = batch[i1];
        if (smemOK) {
            float* sp = spool[g - gFirst] + lane * 4;
            atomicAdd(sp + 0, o0); atomicAdd(sp + 1, o1);
            atomicAdd(sp + 2, o2); atomicAdd(sp + 3, o3);
        } else {
            float* pg = g_pooled + g * FEAT + lane * 4;
            atomicAdd(pg + 0, o0); atomicAdd(pg + 1, o1);
            atomicAdd(pg + 2, o2); atomicAdd(pg + 3, o3);
        }
    }

    __syncthreads();
    if (smemOK) {
        for (int idx = tid; idx < 2 * FEAT; idx += 256) {
            int bank = idx >> 7, c = idx & 127;
            float v = ((float*)spool)[idx];
            int g = gFirst + bank;
            if (v != 0.f && g < NGRAPH)
                atomicAdd(&g_pooled[g * FEAT + c], v);
        }
    }
}

// ---------------- K7: mean + final linear ----------------
__global__ void final_kernel(const int* __restrict__ batch, int Nn,
                             const float* __restrict__ Wl, const float* __restrict__ bl,
                             float* __restrict__ out)
{
    int t = threadIdx.x;
    if (t >= NGRAPH * 2) return;
    int g = t >> 1, o = t & 1;
    int lo = 0, hi = Nn;
    while (lo < hi) { int m = (lo + hi) >> 1; if (batch[m] < g) lo = m + 1; else hi = m; }
    int c0 = lo;
    lo = 0; hi = Nn;
    while (lo < hi) { int m = (lo + hi) >> 1; if (batch[m] < g + 1) lo = m + 1; else hi = m; }
    int cnt = lo - c0;
    float fc = (float)max(cnt, 1);
    float sum = 0.f;
#pragma unroll 4
    for (int k = 0; k < FEAT; k++) sum += g_pooled[g * FEAT + k] * Wl[k * 2 + o];
    out[g * 2 + o] = sum / fc + bl[o];
}

// ---------------- launch ----------------
extern "C" void kernel_launch(void* const* d_in, const int* in_sizes, int n_in,
                              void* d_out, int out_size)
{
    const float* x     = (const float*)d_in[0];
    const int*   ei    = (const int*)d_in[1];     // int32 on the wire
    const int*   batch = (const int*)d_in[2];     // int32 on the wire
    const float* W     = (const float*)d_in[3];
    const float* att_s = (const float*)d_in[4];
    const float* att_d = (const float*)d_in[5];
    const float* bias  = (const float*)d_in[6];
    const float* Wl    = (const float*)d_in[7];
    const float* bl    = (const float*)d_in[8];
    float* out = (float*)d_out;

    int N = in_sizes[0] / FEAT;
    int E = in_sizes[1] / 2;
    int nb = (N + SCAN_BS - 1) / SCAN_BS;

    zero_kernel<<<(N + 255) / 256, 256>>>(N);
    gemm_att_kernel<<<(N + 63) / 64, 256>>>(x, W, att_s, att_d, N);
    hist_kernel<<<(E + 255) / 256, 256>>>(ei, E);
    scan_pass1<<<nb, SCAN_BS>>>(N);
    scan_pass2<<<1, SCAN_BS>>>(nb);
    scan_pass3<<<nb, SCAN_BS>>>(N);
    csr_kernel<<<(E + 255) / 256, 256>>>(ei, E);
    {
        int nblocks = (N + 15) / 16;    // 16 nodes per block (8 warps x 2)
        agg_kernel<<<nblocks, 256>>>(batch, bias, N);
    }
    final_kernel<<<1, 128>>>(batch, N, Wl, bl, out);
}